// round 2
// baseline (speedup 1.0000x reference)
#include <cuda_runtime.h>

// SubglacialDrainageSystem: 64x64 grid, 5-point elliptic solve + closed-form
// sheet-thickness update. Single persistent block, PCG (Jacobi) in shared
// memory, fp64 iteration for robust convergence to the true solution.

#define NN      4096
#define NPAD    (NN + 128)      // +-64 halo padding for stencil gathers
#define NT      1024
#define PER     4               // nodes per thread
#define MAXIT   6000

#define K_COND   0.01
#define SEC_PER_A 31556926.0
#define HR_      0.1
#define LR_      2.0
#define A_       5e-25

struct Smem {
    double xs[NN];
    double rs[NN];
    double qs[NN];
    double ps[NPAD];     // padded: ps[i+64] holds node i
    double red[40];      // reduction scratch (32 warp partials + bcast slot)
    float  diag[NN];
    float  invd[NN];
    float  cE[NPAD];     // cE[i+64]: coupling (i, i+1)
    float  cS[NPAD];     // cS[i+64]: coupling (i, i+64)
};

__device__ __forceinline__ double block_reduce(double v, double* red, int tid) {
    #pragma unroll
    for (int o = 16; o > 0; o >>= 1) v += __shfl_down_sync(0xffffffffu, v, o);
    if ((tid & 31) == 0) red[tid >> 5] = v;
    __syncthreads();
    if (tid < 32) {
        double s = red[tid];
        #pragma unroll
        for (int o = 16; o > 0; o >>= 1) s += __shfl_down_sync(0xffffffffu, s, o);
        if (tid == 0) red[36] = s;
    }
    __syncthreads();
    return red[36];
}

__global__ void __launch_bounds__(NT, 1)
sgd_kernel(const float* __restrict__ base, const float* __restrict__ over,
           const float* __restrict__ melt, const float* __restrict__ sheet,
           const float* __restrict__ pot,  const float* __restrict__ svel,
           const float* __restrict__ llen, const int* __restrict__ lan,
           const int* __restrict__ inflow, float* __restrict__ out)
{
    extern __shared__ unsigned char smraw[];
    Smem& S = *reinterpret_cast<Smem*>(smraw);
    const int tid = threadIdx.x;

    // ---- zero padded arrays ----
    for (int k = tid; k < NPAD; k += NT) { S.cE[k] = 0.f; S.cS[k] = 0.f; S.ps[k] = 0.0; }
    __syncthreads();

    // ---- raw per-link coefficients (E and S links owned by their low node) ----
    #pragma unroll
    for (int nn = 0; nn < PER; nn++) {
        int i = tid + nn * NT;
        int col = i & 63, row = i >> 6;
        double pi = (double)pot[i], hi = (double)sheet[i];
        if (col < 63) {
            double len = (double)llen[row * 63 + col];
            double s = 0.5 * (hi + (double)sheet[i + 1]);
            double g = fabs(pi - (double)pot[i + 1]) / len;
            // c = -K * s^1.25 * len * g^-0.5 ; s^1.25 = s*sqrt(sqrt(s))
            S.cE[i + 64] = (float)(-K_COND * (s * sqrt(sqrt(s))) * len / sqrt(g));
        }
        if (row < 63) {
            double len = (double)llen[4032 + row * 64 + col];
            double s = 0.5 * (hi + (double)sheet[i + 64]);
            double g = fabs(pi - (double)pot[i + 64]) / len;
            S.cS[i + 64] = (float)(-K_COND * (s * sqrt(sqrt(s))) * len / sqrt(g));
        }
    }
    __syncthreads();

    // ---- assemble rows: diag, RHS (fold Dirichlet neighbors), x0, r0 ----
    float newE[PER], newS[PER];
    #pragma unroll
    for (int nn = 0; nn < PER; nn++) {
        int i = tid + nn * NT;
        int col = i & 63, row = i >> 6;
        bool dir = (inflow[i] == 1);
        double cEi = (double)S.cE[i + 64];
        double cWi = (double)S.cE[i + 63];       // cE[i-1]
        double cSi = (double)S.cS[i + 64];
        double cNi = (double)S.cS[i];            // cS[i-64]
        newE[nn] = 0.f; newS[nn] = 0.f;
        if (dir) {
            double val = (double)base[i] - (double)over[i];
            S.diag[i] = 1.0f; S.invd[i] = 1.0f;
            S.xs[i] = val; S.rs[i] = 0.0;
        } else {
            double d = -(cEi + cWi + cSi + cNi);
            double b = (double)melt[i];
            if (col < 63) {
                if (inflow[i + 1] == 1) b -= cEi * ((double)base[i + 1] - (double)over[i + 1]);
                else                    newE[nn] = (float)cEi;
            }
            if (col > 0 && inflow[i - 1] == 1)
                b -= cWi * ((double)base[i - 1] - (double)over[i - 1]);
            if (row < 63) {
                if (inflow[i + 64] == 1) b -= cSi * ((double)base[i + 64] - (double)over[i + 64]);
                else                     newS[nn] = (float)cSi;
            }
            if (row > 0 && inflow[i - 64] == 1)
                b -= cNi * ((double)base[i - 64] - (double)over[i - 64]);
            S.diag[i] = (float)d;
            S.invd[i] = (float)(1.0 / d);
            S.xs[i] = 0.0; S.rs[i] = b;
        }
    }
    __syncthreads();
    // write decoupled (Dirichlet-zeroed) stencil coefficients
    #pragma unroll
    for (int nn = 0; nn < PER; nn++) {
        int i = tid + nn * NT;
        S.cE[i + 64] = newE[nn];
        S.cS[i + 64] = newS[nn];
    }

    // ---- PCG init: p = z = M^-1 r ----
    double rz = 0.0;
    #pragma unroll
    for (int nn = 0; nn < PER; nn++) {
        int i = tid + nn * NT;
        double r = S.rs[i];
        double z = r * (double)S.invd[i];
        S.ps[i + 64] = z;
        rz += r * z;
    }
    __syncthreads();                 // cE/cS + ps visible
    rz = block_reduce(rz, S.red, tid);
    const double rz0 = rz;
    const double tol = rz0 * 1e-20;

    // ---- PCG loop ----
    for (int it = 0; it < MAXIT && rz > tol && rz > 0.0; ++it) {
        // q = A p ; pq = p.q
        double pq = 0.0;
        #pragma unroll
        for (int nn = 0; nn < PER; nn++) {
            int i = tid + nn * NT, ip = i + 64;
            double pv = S.ps[ip];
            double qv = (double)S.diag[i] * pv
                      + (double)S.cE[ip]      * S.ps[ip + 1]
                      + (double)S.cE[ip - 1]  * S.ps[ip - 1]
                      + (double)S.cS[ip]      * S.ps[ip + 64]
                      + (double)S.cS[ip - 64] * S.ps[ip - 64];
            S.qs[i] = qv;
            pq += pv * qv;
        }
        pq = block_reduce(pq, S.red, tid);
        double alpha = rz / pq;

        double z[PER];
        double rznew = 0.0;
        #pragma unroll
        for (int nn = 0; nn < PER; nn++) {
            int i = tid + nn * NT;
            double r = S.rs[i] - alpha * S.qs[i];
            S.rs[i] = r;
            S.xs[i] += alpha * S.ps[i + 64];
            double zz = r * (double)S.invd[i];
            z[nn] = zz;
            rznew += r * zz;
        }
        rznew = block_reduce(rznew, S.red, tid);
        double beta = rznew / rz;
        rz = rznew;
        #pragma unroll
        for (int nn = 0; nn < PER; nn++) {
            int ip = tid + nn * NT + 64;
            S.ps[ip] = z[nn] + beta * S.ps[ip];
        }
        __syncthreads();
    }

    // ---- outputs: potential + closed-form sheet thickness ----
    const double dtf = 3600.0;
    #pragma unroll
    for (int nn = 0; nn < PER; nn++) {
        int i = tid + nn * NT;
        double x = S.xs[i];
        out[i] = (float)x;
        double P = (double)base[i] - x;
        const int* la = lan + 4 * i;
        double ssum = 0.0; int cnt = 0;
        #pragma unroll
        for (int k = 0; k < 4; k++) {
            int l = la[k];
            if (l >= 0) { ssum += (double)svel[l]; cnt++; }
        }
        double sliding = fabs(ssum / SEC_PER_A) / (double)(cnt > 0 ? cnt : 1);
        double nh = ((double)sheet[i] + dtf * sliding * HR_ / LR_)
                  / (1.0 + dtf * (sliding / LR_ + A_ * P * P * P));
        out[NN + i] = (float)nh;
    }
}

extern "C" void kernel_launch(void* const* d_in, const int* in_sizes, int n_in,
                              void* d_out, int out_size)
{
    const float* base  = (const float*)d_in[0];
    const float* over  = (const float*)d_in[1];
    const float* melt  = (const float*)d_in[2];
    const float* sheet = (const float*)d_in[3];
    const float* pot   = (const float*)d_in[4];
    const float* svel  = (const float*)d_in[5];
    const float* llen  = (const float*)d_in[6];
    // d_in[7] link_tail, d_in[8] link_head: implicit in regular grid, unused
    const int*   lan   = (const int*)d_in[9];
    const int*   infl  = (const int*)d_in[10];
    float* out = (float*)d_out;

    int smem = (int)sizeof(Smem);
    cudaFuncSetAttribute(sgd_kernel, cudaFuncAttributeMaxDynamicSharedMemorySize, smem);
    sgd_kernel<<<1, NT, smem>>>(base, over, melt, sheet, pot, svel, llen, lan, infl, out);
}

// round 3
// speedup vs baseline: 17.1656x; 17.1656x over previous
#include <cuda_runtime.h>

// SubglacialDrainageSystem: 64x64 grid, 5-point elliptic solve + closed-form
// sheet-thickness update. Single persistent block. Symmetric Jacobi scaling
// (unit diagonal), fp32 register-resident CG inner solver, fp64 iterative
// refinement outer loop. Coefficients in registers; only p goes through smem.

#define NN      4096
#define NPAD    (NN + 128)      // +-64 halo padding
#define NT      1024
#define PER     4

#define K_COND    0.01
#define SEC_PER_A 31556926.0
#define HR_       0.1
#define LR_       2.0
#define A_        5e-25

struct Smem {
    double cEd[NPAD];   // scaled E coupling (fp64), cEd[i+64] couples i,i+1
    double cSd[NPAD];   // scaled S coupling (fp64), cSd[i+64] couples i,i+64
    double Zs[NPAD];    // master solution (scaled space), padded, halo=0
    double Rd[NN];      // fp64 residual (temp: raw rhs during assembly)
    double Bt[NN];      // scaled rhs b~ (fp64)
    double isd[NN];     // 1/sqrt(diag)
    double red[40];     // fp64 reduction scratch
    float  redf[40];    // fp32 reduction scratch
    float  pf[NPAD];    // CG direction p (fp32), padded, halo=0
};

__device__ __forceinline__ double bred_d(double v, double* red, int tid) {
    #pragma unroll
    for (int o = 16; o > 0; o >>= 1) v += __shfl_down_sync(0xffffffffu, v, o);
    if ((tid & 31) == 0) red[tid >> 5] = v;
    __syncthreads();
    if (tid < 32) {
        double s = red[tid];
        #pragma unroll
        for (int o = 16; o > 0; o >>= 1) s += __shfl_down_sync(0xffffffffu, s, o);
        if (tid == 0) red[36] = s;
    }
    __syncthreads();
    return red[36];
}

__device__ __forceinline__ float bred_f(float v, float* red, int tid) {
    #pragma unroll
    for (int o = 16; o > 0; o >>= 1) v += __shfl_down_sync(0xffffffffu, v, o);
    if ((tid & 31) == 0) red[tid >> 5] = v;
    __syncthreads();
    if (tid < 32) {
        float s = red[tid];
        #pragma unroll
        for (int o = 16; o > 0; o >>= 1) s += __shfl_down_sync(0xffffffffu, s, o);
        if (tid == 0) red[36] = s;
    }
    __syncthreads();
    return red[36];
}

__global__ void __launch_bounds__(NT, 1)
sgd_kernel(const float* __restrict__ base, const float* __restrict__ over,
           const float* __restrict__ melt, const float* __restrict__ sheet,
           const float* __restrict__ pot,  const float* __restrict__ svel,
           const float* __restrict__ llen, const int* __restrict__ lan,
           const int* __restrict__ inflow, float* __restrict__ out)
{
    extern __shared__ unsigned char smraw[];
    Smem& S = *reinterpret_cast<Smem*>(smraw);
    const int tid = threadIdx.x;

    // ---- 1. zero padded arrays ----
    for (int k = tid; k < NPAD; k += NT) {
        S.cEd[k] = 0.0; S.cSd[k] = 0.0; S.Zs[k] = 0.0; S.pf[k] = 0.f;
    }
    __syncthreads();

    // ---- 2. raw per-link coefficients (fp64) ----
    #pragma unroll
    for (int nn = 0; nn < PER; nn++) {
        int i = tid + nn * NT;
        int col = i & 63, row = i >> 6;
        double pi = (double)pot[i], hi = (double)sheet[i];
        if (col < 63) {
            double len = (double)llen[row * 63 + col];
            double s = 0.5 * (hi + (double)sheet[i + 1]);
            double g = fabs(pi - (double)pot[i + 1]) / len;
            S.cEd[i + 64] = -K_COND * (s * sqrt(sqrt(s))) * len / sqrt(g);
        }
        if (row < 63) {
            double len = (double)llen[4032 + row * 64 + col];
            double s = 0.5 * (hi + (double)sheet[i + 64]);
            double g = fabs(pi - (double)pot[i + 64]) / len;
            S.cSd[i + 64] = -K_COND * (s * sqrt(sqrt(s))) * len / sqrt(g);
        }
    }
    __syncthreads();

    // ---- 3. B1: diag, rhs (fold Dirichlet neighbors), scale factors, x0 ----
    #pragma unroll
    for (int nn = 0; nn < PER; nn++) {
        int i = tid + nn * NT;
        int col = i & 63, row = i >> 6;
        bool dir = (inflow[i] == 1);
        double cEi = S.cEd[i + 64];
        double cWi = S.cEd[i + 63];
        double cSi = S.cSd[i + 64];
        double cNi = S.cSd[i];
        double d, b;
        double dval = (double)base[i] - (double)over[i];
        if (dir) {
            d = 1.0; b = dval;
        } else {
            d = -(cEi + cWi + cSi + cNi);
            b = (double)melt[i];
            if (col < 63 && inflow[i + 1] == 1)
                b -= cEi * ((double)base[i + 1] - (double)over[i + 1]);
            if (col > 0 && inflow[i - 1] == 1)
                b -= cWi * ((double)base[i - 1] - (double)over[i - 1]);
            if (row < 63 && inflow[i + 64] == 1)
                b -= cSi * ((double)base[i + 64] - (double)over[i + 64]);
            if (row > 0 && inflow[i - 64] == 1)
                b -= cNi * ((double)base[i - 64] - (double)over[i - 64]);
        }
        double sq = sqrt(d);
        S.isd[i] = 1.0 / sq;
        S.Rd[i] = b;                 // temp: raw rhs
        S.Zs[i + 64] = dval * sq;    // warm start: x0 = base - overburden (scaled)
    }
    __syncthreads();

    // ---- 4. B2: symmetric scaling + Dirichlet decoupling ----
    #pragma unroll
    for (int nn = 0; nn < PER; nn++) {
        int i = tid + nn * NT;
        int col = i & 63, row = i >> 6;
        bool dirI = (inflow[i] == 1);
        if (col < 63) {
            bool dirE = (inflow[i + 1] == 1);
            S.cEd[i + 64] = (dirI || dirE) ? 0.0
                          : S.cEd[i + 64] * S.isd[i] * S.isd[i + 1];
        }
        if (row < 63) {
            bool dirS = (inflow[i + 64] == 1);
            S.cSd[i + 64] = (dirI || dirS) ? 0.0
                          : S.cSd[i + 64] * S.isd[i] * S.isd[i + 64];
        }
        S.Bt[i] = S.Rd[i] * S.isd[i];
    }
    __syncthreads();

    // ---- 5. fp32 coefficient registers (block mapping: thread owns 4 consecutive) ----
    const int ib = tid * 4;
    const int ip = ib + 64;
    const float cWe = (float)S.cEd[ip - 1];
    const float c01 = (float)S.cEd[ip + 0];
    const float c12 = (float)S.cEd[ip + 1];
    const float c23 = (float)S.cEd[ip + 2];
    const float cEe = (float)S.cEd[ip + 3];
    const float cN0 = (float)S.cSd[ip - 64], cN1 = (float)S.cSd[ip - 63];
    const float cN2 = (float)S.cSd[ip - 62], cN3 = (float)S.cSd[ip - 61];
    const float cS0 = (float)S.cSd[ip + 0], cS1 = (float)S.cSd[ip + 1];
    const float cS2 = (float)S.cSd[ip + 2], cS3 = (float)S.cSd[ip + 3];

    double sb = 0.0;
    #pragma unroll
    for (int nn = 0; nn < PER; nn++) { double v = S.Bt[ib + nn]; sb += v * v; }
    const double rzb = bred_d(sb, S.red, tid);
    const double rz_target = rzb * 1e-18;

    float4* pf4 = reinterpret_cast<float4*>(S.pf);   // pf4[k] = pf[4k]

    // ---- 6. outer refinement passes ----
    for (int pass = 0; pass < 3; ++pass) {
        // fp64 residual of scaled system
        double rdv[PER];
        double rr = 0.0;
        #pragma unroll
        for (int nn = 0; nn < PER; nn++) {
            int i = ib + nn, j = ip + nn;
            double q = S.Zs[j]
                     + S.cEd[j]      * S.Zs[j + 1]
                     + S.cEd[j - 1]  * S.Zs[j - 1]
                     + S.cSd[j]      * S.Zs[j + 64]
                     + S.cSd[j - 64] * S.Zs[j - 64];
            double rv = S.Bt[i] - q;
            rdv[nn] = rv;
            rr += rv * rv;
        }
        rr = bred_d(rr, S.red, tid);
        if (!(rr > rz_target)) break;

        // fp32 CG on correction system
        float r0 = (float)rdv[0], r1 = (float)rdv[1];
        float r2 = (float)rdv[2], r3 = (float)rdv[3];
        float p0 = r0, p1 = r1, p2 = r2, p3 = r3;
        float dx0 = 0.f, dx1 = 0.f, dx2 = 0.f, dx3 = 0.f;
        pf4[tid + 16] = make_float4(p0, p1, p2, p3);   // +16 float4 = +64 floats
        float rz = bred_f(r0*r0 + r1*r1 + r2*r2 + r3*r3, S.redf, tid);

        const float tolp = fmaxf((float)rz_target, rz * 1e-12f);
        const int cap = (pass == 0) ? 2500 : ((pass == 1) ? 1800 : 1200);
        float rzchk = rz;

        for (int it = 0; it < cap && rz > tolp; ++it) {
            // q = A~ p (unit diagonal)
            float  pW = S.pf[ip - 1];
            float  pE = S.pf[ip + 4];
            float4 pN = pf4[tid + 0];     // pf[ip-64 .. ]
            float4 pS = pf4[tid + 32];    // pf[ip+64 .. ]
            float q0 = p0 + cWe*pW + c01*p1 + cN0*pN.x + cS0*pS.x;
            float q1 = p1 + c01*p0 + c12*p2 + cN1*pN.y + cS1*pS.y;
            float q2 = p2 + c12*p1 + c23*p3 + cN2*pN.z + cS2*pS.z;
            float q3 = p3 + c23*p2 + cEe*pE + cN3*pN.w + cS3*pS.w;
            float pq = bred_f(p0*q0 + p1*q1 + p2*q2 + p3*q3, S.redf, tid);
            if (!(pq > 0.f)) break;
            float alpha = rz / pq;

            r0 -= alpha * q0; r1 -= alpha * q1;
            r2 -= alpha * q2; r3 -= alpha * q3;
            dx0 += alpha * p0; dx1 += alpha * p1;
            dx2 += alpha * p2; dx3 += alpha * p3;
            float rznew = bred_f(r0*r0 + r1*r1 + r2*r2 + r3*r3, S.redf, tid);
            float beta = rznew / rz;
            rz = rznew;
            p0 = r0 + beta * p0; p1 = r1 + beta * p1;
            p2 = r2 + beta * p2; p3 = r3 + beta * p3;
            pf4[tid + 16] = make_float4(p0, p1, p2, p3);
            __syncthreads();

            // stagnation guard: <10% progress over 256 iters -> stop this pass
            if ((it & 255) == 255) {
                if (rz > 0.9f * rzchk) break;
                rzchk = rz;
            }
        }

        // accumulate correction into fp64 master
        S.Zs[ip + 0] += (double)dx0;
        S.Zs[ip + 1] += (double)dx1;
        S.Zs[ip + 2] += (double)dx2;
        S.Zs[ip + 3] += (double)dx3;
        __syncthreads();
    }

    // ---- 7. outputs: potential + closed-form sheet thickness ----
    const double dtf = 3600.0;
    #pragma unroll
    for (int nn = 0; nn < PER; nn++) {
        int i = ib + nn;
        double x = S.Zs[ip + nn] * S.isd[i];
        out[i] = (float)x;
        double P = (double)base[i] - x;
        const int* la = lan + 4 * i;
        double ssum = 0.0; int cnt = 0;
        #pragma unroll
        for (int k = 0; k < 4; k++) {
            int l = la[k];
            if (l >= 0) { ssum += (double)svel[l]; cnt++; }
        }
        double sliding = fabs(ssum / SEC_PER_A) / (double)(cnt > 0 ? cnt : 1);
        double nh = ((double)sheet[i] + dtf * sliding * HR_ / LR_)
                  / (1.0 + dtf * (sliding / LR_ + A_ * P * P * P));
        out[NN + i] = (float)nh;
    }
}

extern "C" void kernel_launch(void* const* d_in, const int* in_sizes, int n_in,
                              void* d_out, int out_size)
{
    const float* base  = (const float*)d_in[0];
    const float* over  = (const float*)d_in[1];
    const float* melt  = (const float*)d_in[2];
    const float* sheet = (const float*)d_in[3];
    const float* pot   = (const float*)d_in[4];
    const float* svel  = (const float*)d_in[5];
    const float* llen  = (const float*)d_in[6];
    const int*   lan   = (const int*)d_in[9];
    const int*   infl  = (const int*)d_in[10];
    float* out = (float*)d_out;

    int smem = (int)sizeof(Smem);
    cudaFuncSetAttribute(sgd_kernel, cudaFuncAttributeMaxDynamicSharedMemorySize, smem);
    sgd_kernel<<<1, NT, smem>>>(base, over, melt, sheet, pot, svel, llen, lan, infl, out);
}

// round 9
// speedup vs baseline: 19.1203x; 1.1139x over previous
#include <cuda_runtime.h>

// SubglacialDrainageSystem: 64x64 grid, 5-point elliptic solve + closed-form
// sheet-thickness update. Single persistent block (512 thr, 8 nodes/thread).
// Symmetric Jacobi scaling (unit diagonal), fp32 pipelined (Chronopoulos-Gear)
// CG with ONE fused reduction and TWO __syncthreads per iteration; fp64
// iterative-refinement outer loop.
// R5 fix: p/q explicitly zero-initialized (uninitialized regs * beta=0 could
// inject NaN at it=0).

#define NN      4096
#define NPAD    (NN + 128)      // +-64 halo padding
#define NT      512
#define PER     8

#define K_COND    0.01
#define SEC_PER_A 31556926.0
#define HR_       0.1
#define LR_       2.0
#define A_        5e-25

struct Smem {
    double cEd[NPAD];   // scaled E coupling (fp64), cEd[i+64] couples i,i+1
    double cSd[NPAD];   // scaled S coupling (fp64), cSd[i+64] couples i,i+64
    double Zs[NPAD];    // master solution (scaled space), padded, halo=0
    double Rd[NN];      // temp raw rhs
    double Bt[NN];      // scaled rhs (fp64)
    double isd[NN];     // 1/sqrt(diag)
    double red[40];     // fp64 reduction scratch (slots 16..31 stay zero)
    float  redf[64];    // fp32 fused reduction scratch (16..31, 48..63 stay zero)
    float  rf[NPAD];    // CG residual r (fp32), padded, halo=0
};

__device__ __forceinline__ double bred_d(double v, double* red, int tid) {
    #pragma unroll
    for (int o = 16; o > 0; o >>= 1) v += __shfl_down_sync(0xffffffffu, v, o);
    if ((tid & 31) == 0) red[tid >> 5] = v;
    __syncthreads();
    if (tid < 32) {
        double s = red[tid];   // slots 16..31 are zero
        #pragma unroll
        for (int o = 16; o > 0; o >>= 1) s += __shfl_down_sync(0xffffffffu, s, o);
        if (tid == 0) red[36] = s;
    }
    __syncthreads();
    return red[36];
}

// Fused 2-component block reduction, ONE __syncthreads. All lanes return sum.
__device__ __forceinline__ float2 bred2f(float a, float b, float* red, int tid) {
    #pragma unroll
    for (int o = 16; o > 0; o >>= 1) {
        a += __shfl_down_sync(0xffffffffu, a, o);
        b += __shfl_down_sync(0xffffffffu, b, o);
    }
    if ((tid & 31) == 0) { int w = tid >> 5; red[w] = a; red[32 + w] = b; }
    __syncthreads();
    int l = tid & 31;
    float x = red[l], y = red[32 + l];   // 16..31 / 48..63 are zero
    #pragma unroll
    for (int o = 16; o > 0; o >>= 1) {
        x += __shfl_xor_sync(0xffffffffu, x, o);
        y += __shfl_xor_sync(0xffffffffu, y, o);
    }
    return make_float2(x, y);
}

__global__ void __launch_bounds__(NT, 1)
sgd_kernel(const float* __restrict__ base, const float* __restrict__ over,
           const float* __restrict__ melt, const float* __restrict__ sheet,
           const float* __restrict__ pot,  const float* __restrict__ svel,
           const float* __restrict__ llen, const int* __restrict__ lan,
           const int* __restrict__ inflow, float* __restrict__ out)
{
    extern __shared__ unsigned char smraw[];
    Smem& S = *reinterpret_cast<Smem*>(smraw);
    const int tid = threadIdx.x;

    // ---- 1. zero padded arrays + reduction scratch ----
    for (int k = tid; k < NPAD; k += NT) {
        S.cEd[k] = 0.0; S.cSd[k] = 0.0; S.Zs[k] = 0.0; S.rf[k] = 0.f;
    }
    if (tid < 40) S.red[tid] = 0.0;
    if (tid < 64) S.redf[tid] = 0.f;
    __syncthreads();

    // ---- 2. raw per-link coefficients (fp64) ----
    #pragma unroll
    for (int nn = 0; nn < PER; nn++) {
        int i = tid + nn * NT;
        int col = i & 63, row = i >> 6;
        double pi = (double)pot[i], hi = (double)sheet[i];
        if (col < 63) {
            double len = (double)llen[row * 63 + col];
            double s = 0.5 * (hi + (double)sheet[i + 1]);
            double g = fabs(pi - (double)pot[i + 1]) / len;
            S.cEd[i + 64] = -K_COND * (s * sqrt(sqrt(s))) * len / sqrt(g);
        }
        if (row < 63) {
            double len = (double)llen[4032 + row * 64 + col];
            double s = 0.5 * (hi + (double)sheet[i + 64]);
            double g = fabs(pi - (double)pot[i + 64]) / len;
            S.cSd[i + 64] = -K_COND * (s * sqrt(sqrt(s))) * len / sqrt(g);
        }
    }
    __syncthreads();

    // ---- 3. diag, rhs (fold Dirichlet neighbors), scale factors, warm start ----
    #pragma unroll
    for (int nn = 0; nn < PER; nn++) {
        int i = tid + nn * NT;
        int col = i & 63, row = i >> 6;
        bool dir = (inflow[i] == 1);
        double cEi = S.cEd[i + 64];
        double cWi = S.cEd[i + 63];
        double cSi = S.cSd[i + 64];
        double cNi = S.cSd[i];
        double d, b;
        double dval = (double)base[i] - (double)over[i];
        if (dir) {
            d = 1.0; b = dval;
        } else {
            d = -(cEi + cWi + cSi + cNi);
            b = (double)melt[i];
            if (col < 63 && inflow[i + 1] == 1)
                b -= cEi * ((double)base[i + 1] - (double)over[i + 1]);
            if (col > 0 && inflow[i - 1] == 1)
                b -= cWi * ((double)base[i - 1] - (double)over[i - 1]);
            if (row < 63 && inflow[i + 64] == 1)
                b -= cSi * ((double)base[i + 64] - (double)over[i + 64]);
            if (row > 0 && inflow[i - 64] == 1)
                b -= cNi * ((double)base[i - 64] - (double)over[i - 64]);
        }
        double sq = sqrt(d);
        S.isd[i] = 1.0 / sq;
        S.Rd[i] = b;
        S.Zs[i + 64] = dval * sq;    // warm start (scaled): x0 = base - overburden
    }
    __syncthreads();

    // ---- 4. symmetric scaling + Dirichlet decoupling ----
    #pragma unroll
    for (int nn = 0; nn < PER; nn++) {
        int i = tid + nn * NT;
        int col = i & 63, row = i >> 6;
        bool dirI = (inflow[i] == 1);
        if (col < 63) {
            bool dirE = (inflow[i + 1] == 1);
            S.cEd[i + 64] = (dirI || dirE) ? 0.0
                          : S.cEd[i + 64] * S.isd[i] * S.isd[i + 1];
        }
        if (row < 63) {
            bool dirS = (inflow[i + 64] == 1);
            S.cSd[i + 64] = (dirI || dirS) ? 0.0
                          : S.cSd[i + 64] * S.isd[i] * S.isd[i + 64];
        }
        S.Bt[i] = S.Rd[i] * S.isd[i];
    }
    __syncthreads();

    // ---- 5. fp32 coefficient registers: thread owns 8 consecutive nodes ----
    const int ib = tid * 8;
    const int ip = ib + 64;
    float cW = (float)S.cEd[ip - 1];
    float cEa = (float)S.cEd[ip + 7];
    float cI[7], cN[8], cS[8];
    #pragma unroll
    for (int j = 0; j < 7; j++) cI[j] = (float)S.cEd[ip + j];
    #pragma unroll
    for (int j = 0; j < 8; j++) { cN[j] = (float)S.cSd[ip - 64 + j]; cS[j] = (float)S.cSd[ip + j]; }

    double sb = 0.0;
    #pragma unroll
    for (int nn = 0; nn < PER; nn++) { double v = S.Bt[ib + nn]; sb += v * v; }
    const double rzb = bred_d(sb, S.red, tid);
    const double rz_target = rzb * 1e-16;

    float4* rf4 = reinterpret_cast<float4*>(S.rf);    // rf4[k] = rf[4k]
    const int own4 = tid * 2 + 16;                    // own nodes start (float4 units)

    // ---- 6. outer refinement passes ----
    for (int pass = 0; pass < 4; ++pass) {
        // fp64 residual of scaled system
        double rdv[PER];
        double rr = 0.0;
        #pragma unroll
        for (int nn = 0; nn < PER; nn++) {
            int i = ib + nn, j = ip + nn;
            double q = S.Zs[j]
                     + S.cEd[j]      * S.Zs[j + 1]
                     + S.cEd[j - 1]  * S.Zs[j - 1]
                     + S.cSd[j]      * S.Zs[j + 64]
                     + S.cSd[j - 64] * S.Zs[j - 64];
            double rv = S.Bt[i] - q;
            rdv[nn] = rv;
            rr += rv * rv;
        }
        rr = bred_d(rr, S.red, tid);
        if (!(rr > rz_target)) break;

        // ---- fp32 pipelined CG (Chronopoulos-Gear) on correction system ----
        float r[PER], p[PER], q[PER], dx[PER];
        #pragma unroll
        for (int nn = 0; nn < PER; nn++) {
            r[nn] = (float)rdv[nn];
            p[nn] = 0.f;           // FIX: explicit init (beta=0 * garbage != 0)
            q[nn] = 0.f;
            dx[nn] = 0.f;
        }
        rf4[own4 + 0] = make_float4(r[0], r[1], r[2], r[3]);
        rf4[own4 + 1] = make_float4(r[4], r[5], r[6], r[7]);
        __syncthreads();

        const float tolp = fmaxf((float)rz_target, (float)rr * 1e-12f);
        const int cap = (pass == 0) ? 3000 : ((pass == 1) ? 2000 : 1200);
        float rho_old = 1.f, gam = 0.f;
        float rzchk = (float)rr;

        for (int it = 0; it < cap; ++it) {
            // w = A~ r  (unit diagonal)
            float  rW = S.rf[ip - 1];
            float  rE = S.rf[ip + 8];
            float4 n0 = rf4[own4 - 16], n1 = rf4[own4 - 15];  // row above
            float4 s0 = rf4[own4 + 16], s1 = rf4[own4 + 17];  // row below
            float w[PER];
            w[0] = r[0] + cW   *rW   + cI[0]*r[1] + cN[0]*n0.x + cS[0]*s0.x;
            w[1] = r[1] + cI[0]*r[0] + cI[1]*r[2] + cN[1]*n0.y + cS[1]*s0.y;
            w[2] = r[2] + cI[1]*r[1] + cI[2]*r[3] + cN[2]*n0.z + cS[2]*s0.z;
            w[3] = r[3] + cI[2]*r[2] + cI[3]*r[4] + cN[3]*n0.w + cS[3]*s0.w;
            w[4] = r[4] + cI[3]*r[3] + cI[4]*r[5] + cN[4]*n1.x + cS[4]*s1.x;
            w[5] = r[5] + cI[4]*r[4] + cI[5]*r[6] + cN[5]*n1.y + cS[5]*s1.y;
            w[6] = r[6] + cI[5]*r[5] + cI[6]*r[7] + cN[6]*n1.z + cS[6]*s1.z;
            w[7] = r[7] + cI[6]*r[6] + cEa  *rE   + cN[7]*n1.w + cS[7]*s1.w;

            float prho = 0.f, pmu = 0.f;
            #pragma unroll
            for (int nn = 0; nn < PER; nn++) { prho += r[nn]*r[nn]; pmu += r[nn]*w[nn]; }
            float2 d2 = bred2f(prho, pmu, S.redf, tid);   // sync A inside
            float rho = d2.x, mu = d2.y;

            if (rho <= tolp) break;
            if ((it & 255) == 255) {                      // stagnation guard
                if (rho > 0.9f * rzchk) break;
                rzchk = rho;
            }

            float beta = (it == 0) ? 0.f : __fdividef(rho, rho_old);
            gam = __fdividef(mu, rho) - beta * gam;       // gam = 1/alpha
            if (!(gam > 0.f)) break;
            float alpha = __fdividef(1.f, gam);
            rho_old = rho;

            #pragma unroll
            for (int nn = 0; nn < PER; nn++) {
                p[nn] = r[nn] + beta * p[nn];
                q[nn] = w[nn] + beta * q[nn];
                dx[nn] += alpha * p[nn];
                r[nn]  -= alpha * q[nn];
            }
            rf4[own4 + 0] = make_float4(r[0], r[1], r[2], r[3]);
            rf4[own4 + 1] = make_float4(r[4], r[5], r[6], r[7]);
            __syncthreads();                              // sync B
        }

        // accumulate correction into fp64 master
        __syncthreads();
        #pragma unroll
        for (int nn = 0; nn < PER; nn++) S.Zs[ip + nn] += (double)dx[nn];
        __syncthreads();
    }

    // ---- 7. outputs: potential + closed-form sheet thickness ----
    const double dtf = 3600.0;
    #pragma unroll
    for (int nn = 0; nn < PER; nn++) {
        int i = ib + nn;
        double x = S.Zs[ip + nn] * S.isd[i];
        out[i] = (float)x;
        double P = (double)base[i] - x;
        const int* la = lan + 4 * i;
        double ssum = 0.0; int cnt = 0;
        #pragma unroll
        for (int k = 0; k < 4; k++) {
            int l = la[k];
            if (l >= 0) { ssum += (double)svel[l]; cnt++; }
        }
        double sliding = fabs(ssum / SEC_PER_A) / (double)(cnt > 0 ? cnt : 1);
        double nh = ((double)sheet[i] + dtf * sliding * HR_ / LR_)
                  / (1.0 + dtf * (sliding / LR_ + A_ * P * P * P));
        out[NN + i] = (float)nh;
    }
}

extern "C" void kernel_launch(void* const* d_in, const int* in_sizes, int n_in,
                              void* d_out, int out_size)
{
    const float* base  = (const float*)d_in[0];
    const float* over  = (const float*)d_in[1];
    const float* melt  = (const float*)d_in[2];
    const float* sheet = (const float*)d_in[3];
    const float* pot   = (const float*)d_in[4];
    const float* svel  = (const float*)d_in[5];
    const float* llen  = (const float*)d_in[6];
    const int*   lan   = (const int*)d_in[9];
    const int*   infl  = (const int*)d_in[10];
    float* out = (float*)d_out;

    int smem = (int)sizeof(Smem);
    cudaFuncSetAttribute(sgd_kernel, cudaFuncAttributeMaxDynamicSharedMemorySize, smem);
    sgd_kernel<<<1, NT, smem>>>(base, over, melt, sheet, pot, svel, llen, lan, infl, out);
}